// round 3
// baseline (speedup 1.0000x reference)
#include <cuda_runtime.h>
#include <math.h>

#define NN 100000
#define EE 1000000

// ---------------- device scratch ----------------
__device__ int    d_cnt[NN];
__device__ int    d_off[NN + 1];
__device__ int    d_cur[NN];
__device__ int    d_scan_tix;
__device__ unsigned long long d_scan_state[128];
__device__ int    d_eid[EE];
__device__ int    d_pid[EE];
__device__ int    d_ssrc[EE];
__device__ float  d_hagg0[(size_t)NN * 64];
__device__ float  d_efp [(size_t)NN * 64];
__device__ float  d_efn [(size_t)NN * 64];
__device__ float  d_h1p [(size_t)NN * 64];
__device__ float  d_h1n [(size_t)NN * 64];
__device__ float  d_hp  [(size_t)NN * 64];
__device__ float  d_hn  [(size_t)NN * 64];
__device__ float  d_Wc[2][192 * 64];
__device__ float  d_cv[2][64];
__device__ double d_loss;

// ---------------- f32x2 helpers ----------------
typedef unsigned long long u64;

__device__ __forceinline__ u64 pack2(float x) {
    u64 r; asm("mov.b64 %0,{%1,%1};" : "=l"(r) : "f"(x)); return r;
}
__device__ __forceinline__ void fma2(u64& acc, u64 a, u64 b) {
    asm("fma.rn.f32x2 %0, %1, %2, %0;" : "+l"(acc) : "l"(a), "l"(b));
}
__device__ __forceinline__ float2 unpack2(u64 v) {
    float2 r; asm("mov.b64 {%0,%1},%2;" : "=f"(r.x), "=f"(r.y) : "l"(v)); return r;
}

// ---------------- init ----------------
__global__ void k_init(int n) {
    int i = blockIdx.x * blockDim.x + threadIdx.x;
    if (i < n) { d_cnt[i] = 0; d_cur[i] = 0; }
    if (i < 128) d_scan_state[i] = 0ULL;
    if (i == 0) { d_loss = 0.0; d_scan_tix = 0; }
}

__global__ void k_hist(const int* __restrict__ dst, int E) {
    int e = blockIdx.x * blockDim.x + threadIdx.x;
    if (e < E) atomicAdd(&d_cnt[dst[e]], 1);
}

// ---------------- single-pass decoupled-lookback scan ----------------
__global__ void k_scan(int n, int E, int nb) {
    __shared__ int ws[32];
    __shared__ int s_bid;
    __shared__ int s_pref;
    if (threadIdx.x == 0) s_bid = atomicAdd(&d_scan_tix, 1);
    __syncthreads();
    int bid = s_bid;
    int i = bid * 1024 + threadIdx.x;
    int lane = threadIdx.x & 31, wid = threadIdx.x >> 5;
    int v = (i < n) ? d_cnt[i] : 0;
    int x = v;
    #pragma unroll
    for (int o = 1; o < 32; o <<= 1) { int y = __shfl_up_sync(~0u, x, o); if (lane >= o) x += y; }
    if (lane == 31) ws[wid] = x;
    __syncthreads();
    if (wid == 0) {
        int w = ws[lane];
        #pragma unroll
        for (int o = 1; o < 32; o <<= 1) { int y = __shfl_up_sync(~0u, w, o); if (lane >= o) w += y; }
        ws[lane] = w;
    }
    __syncthreads();
    int incl = x + (wid > 0 ? ws[wid - 1] : 0);
    int total = ws[31];

    if (threadIdx.x == 0) {
        if (bid == 0) {
            atomicExch(&d_scan_state[0], (2ULL << 32) | (unsigned)total);
            s_pref = 0;
        } else {
            atomicExch(&d_scan_state[bid], (1ULL << 32) | (unsigned)total);
            int pref = 0;
            for (int j = bid - 1; j >= 0; --j) {
                unsigned long long st;
                do { st = atomicAdd(&d_scan_state[j], 0ULL); } while (!(st >> 32));
                pref += (int)(unsigned)st;
                if ((st >> 32) == 2ULL) break;
            }
            atomicExch(&d_scan_state[bid], (2ULL << 32) | (unsigned)(pref + total));
            s_pref = pref;
        }
    }
    __syncthreads();
    int pref = s_pref;
    if (i < n) d_off[i] = pref + incl - v;
    if (bid == nb - 1 && threadIdx.x == 0) d_off[n] = E;
}

__global__ void k_scatter(const int* __restrict__ src, const int* __restrict__ dst,
                          const int* __restrict__ perm, int E) {
    int e = blockIdx.x * blockDim.x + threadIdx.x;
    if (e < E) {
        int d = dst[e];
        int p = d_off[d] + atomicAdd(&d_cur[d], 1);
        d_eid[p]  = e;
        d_pid[p]  = perm[e];
        d_ssrc[p] = src[e];
    }
}

// ---------------- fold Wmsg into Wapply (both layers, blockIdx = layer) ----------------
__global__ void k_fold2(const float* __restrict__ Wm0, const float* __restrict__ bm0,
                        const float* __restrict__ Wa0,
                        const float* __restrict__ Wm1, const float* __restrict__ bm1,
                        const float* __restrict__ Wa1) {
    int layer = blockIdx.x;
    const float* Wmsg = layer ? Wm1 : Wm0;
    const float* bmsg = layer ? bm1 : bm0;
    const float* Wap  = layer ? Wa1 : Wa0;
    __shared__ float Wn[64][64];
    __shared__ float bm[64];
    int tid = threadIdx.x;
    for (int idx = tid; idx < 64 * 64; idx += 256) {
        int j = idx >> 6, t = idx & 63;
        Wn[t][j] = Wap[j * 128 + 64 + t];
    }
    if (tid < 64) bm[tid] = bmsg[tid];
    __syncthreads();
    for (int idx = tid; idx < 192 * 64; idx += 256) {
        int k = idx >> 6, j = idx & 63;
        float r;
        if (k < 64) {
            r = Wap[j * 128 + k];
        } else {
            int col = k - 64;
            float a = 0.f;
            #pragma unroll
            for (int t = 0; t < 64; ++t) a += Wmsg[t * 128 + col] * Wn[t][j];
            r = a;
        }
        d_Wc[layer][k * 64 + j] = r;
    }
    for (int j = tid; j < 64; j += 256) {
        float a = 0.f;
        #pragma unroll
        for (int t = 0; t < 64; ++t) a += bm[t] * Wn[t][j];
        d_cv[layer][j] = a;
    }
}

// ---------------- fused first-stage aggregation: hagg0 + efp + efn ----------------
// half-warp/float4 layout: lanes 0-15 handle even positions, 16-31 odd; 2 edges in flight.
__global__ void k_agg3(const float* __restrict__ nfeats, const float* __restrict__ ef,
                       float* __restrict__ hagg0, float* __restrict__ efp,
                       float* __restrict__ efn, int n) {
    int gw = (blockIdx.x * blockDim.x + threadIdx.x) >> 5;
    int lane = threadIdx.x & 31;
    if (gw >= n) return;
    int beg = d_off[gw], end = d_off[gw + 1];
    int half = lane >> 4;
    int c4 = (lane & 15) << 2;
    float4 ah = make_float4(0.f, 0.f, 0.f, 0.f);
    float4 ap = ah, an = ah;
    for (int k = beg + half; k < end; k += 2) {
        int s  = __ldg(&d_ssrc[k]);
        int e  = __ldg(&d_eid[k]);
        int pe = __ldg(&d_pid[k]);
        float4 v1 = *reinterpret_cast<const float4*>(nfeats + (size_t)s  * 64 + c4);
        float4 v2 = *reinterpret_cast<const float4*>(ef     + (size_t)e  * 64 + c4);
        float4 v3 = *reinterpret_cast<const float4*>(ef     + (size_t)pe * 64 + c4);
        ah.x += v1.x; ah.y += v1.y; ah.z += v1.z; ah.w += v1.w;
        ap.x += v2.x; ap.y += v2.y; ap.z += v2.z; ap.w += v2.w;
        an.x += v3.x; an.y += v3.y; an.z += v3.z; an.w += v3.w;
    }
    ah.x += __shfl_xor_sync(~0u, ah.x, 16); ah.y += __shfl_xor_sync(~0u, ah.y, 16);
    ah.z += __shfl_xor_sync(~0u, ah.z, 16); ah.w += __shfl_xor_sync(~0u, ah.w, 16);
    ap.x += __shfl_xor_sync(~0u, ap.x, 16); ap.y += __shfl_xor_sync(~0u, ap.y, 16);
    ap.z += __shfl_xor_sync(~0u, ap.z, 16); ap.w += __shfl_xor_sync(~0u, ap.w, 16);
    an.x += __shfl_xor_sync(~0u, an.x, 16); an.y += __shfl_xor_sync(~0u, an.y, 16);
    an.z += __shfl_xor_sync(~0u, an.z, 16); an.w += __shfl_xor_sync(~0u, an.w, 16);
    float inv = 1.f / fmaxf((float)(end - beg), 1.f);
    if (half == 0) {
        *reinterpret_cast<float4*>(hagg0 + (size_t)gw * 64 + c4) =
            make_float4(ah.x * inv, ah.y * inv, ah.z * inv, ah.w * inv);
        *reinterpret_cast<float4*>(efp + (size_t)gw * 64 + c4) =
            make_float4(ap.x * inv, ap.y * inv, ap.z * inv, ap.w * inv);
        *reinterpret_cast<float4*>(efn + (size_t)gw * 64 + c4) =
            make_float4(an.x * inv, an.y * inv, an.z * inv, an.w * inv);
    }
}

// ---------------- second-stage aggregation: hp + hn (same ssrc index list) ----------------
__global__ void k_aggh2(const float* __restrict__ fa, const float* __restrict__ fb,
                        float* __restrict__ oa, float* __restrict__ ob, int n) {
    int gw = (blockIdx.x * blockDim.x + threadIdx.x) >> 5;
    int lane = threadIdx.x & 31;
    if (gw >= n) return;
    int beg = d_off[gw], end = d_off[gw + 1];
    int half = lane >> 4;
    int c4 = (lane & 15) << 2;
    float4 aa = make_float4(0.f, 0.f, 0.f, 0.f);
    float4 ab = aa;
    for (int k = beg + half; k < end; k += 2) {
        int s = __ldg(&d_ssrc[k]);
        float4 v1 = *reinterpret_cast<const float4*>(fa + (size_t)s * 64 + c4);
        float4 v2 = *reinterpret_cast<const float4*>(fb + (size_t)s * 64 + c4);
        aa.x += v1.x; aa.y += v1.y; aa.z += v1.z; aa.w += v1.w;
        ab.x += v2.x; ab.y += v2.y; ab.z += v2.z; ab.w += v2.w;
    }
    aa.x += __shfl_xor_sync(~0u, aa.x, 16); aa.y += __shfl_xor_sync(~0u, aa.y, 16);
    aa.z += __shfl_xor_sync(~0u, aa.z, 16); aa.w += __shfl_xor_sync(~0u, aa.w, 16);
    ab.x += __shfl_xor_sync(~0u, ab.x, 16); ab.y += __shfl_xor_sync(~0u, ab.y, 16);
    ab.z += __shfl_xor_sync(~0u, ab.z, 16); ab.w += __shfl_xor_sync(~0u, ab.w, 16);
    float inv = 1.f / fmaxf((float)(end - beg), 1.f);
    if (half == 0) {
        *reinterpret_cast<float4*>(oa + (size_t)gw * 64 + c4) =
            make_float4(aa.x * inv, aa.y * inv, aa.z * inv, aa.w * inv);
        *reinterpret_cast<float4*>(ob + (size_t)gw * 64 + c4) =
            make_float4(ab.x * inv, ab.y * inv, ab.z * inv, ab.w * inv);
    }
}

// ---------------- GEMM building blocks ----------------
// Tile: 64 rows x 64 cols, 256 threads. Thread (rowg=tid>>2, colg=tid&3) owns
// row rowg, cols { colg*4 + m*16 + 0..3 : m=0..3 } -> acc u64[8].
// Full folded W (192x64 = 48KB) resident in smem; X staged per 64-k phase.

#define XSTRIDE 68
#define LAYER_SMEM (192 * 64 * 4 + 64 * XSTRIDE * 4)

__device__ __forceinline__ void stageX(float* __restrict__ Xs, const float* __restrict__ S,
                                       int node0, int n, int tid) {
    #pragma unroll
    for (int it = 0; it < 4; ++it) {
        int t = tid + it * 256;
        int r = t >> 4, c4 = (t & 15) << 2;
        int nd = node0 + r;
        float4 v = make_float4(0.f, 0.f, 0.f, 0.f);
        if (nd < n) v = *reinterpret_cast<const float4*>(S + (size_t)nd * 64 + c4);
        *reinterpret_cast<float4*>(Xs + r * XSTRIDE + c4) = v;
    }
}

__device__ __forceinline__ void phase64(const float* __restrict__ Xs, const float* __restrict__ Wp,
                                        u64* acc, int rowg, int cbase) {
    #pragma unroll 8
    for (int k = 0; k < 64; ++k) {
        u64 xx = pack2(Xs[rowg * XSTRIDE + k]);
        const float* wr = Wp + k * 64 + cbase;
        ulonglong2 w0 = *reinterpret_cast<const ulonglong2*>(wr);
        ulonglong2 w1 = *reinterpret_cast<const ulonglong2*>(wr + 16);
        ulonglong2 w2 = *reinterpret_cast<const ulonglong2*>(wr + 32);
        ulonglong2 w3 = *reinterpret_cast<const ulonglong2*>(wr + 48);
        fma2(acc[0], xx, w0.x); fma2(acc[1], xx, w0.y);
        fma2(acc[2], xx, w1.x); fma2(acc[3], xx, w1.y);
        fma2(acc[4], xx, w2.x); fma2(acc[5], xx, w2.y);
        fma2(acc[6], xx, w3.x); fma2(acc[7], xx, w3.y);
    }
}

__device__ __forceinline__ void epi_store(const u64* acc, const float* __restrict__ bap,
                                          const float* __restrict__ cv, float* __restrict__ out,
                                          int nd, int cbase, int n) {
    if (nd >= n) return;
    float ind = (d_cnt[nd] > 0) ? 1.f : 0.f;
    #pragma unroll
    for (int m = 0; m < 4; ++m) {
        int c = cbase + (m << 4);
        float2 a = unpack2(acc[2 * m]);
        float2 b = unpack2(acc[2 * m + 1]);
        float4 bb = *reinterpret_cast<const float4*>(bap + c);
        float4 cc = *reinterpret_cast<const float4*>(cv + c);
        float4 o;
        o.x = fmaxf(a.x + bb.x + ind * cc.x, 0.f);
        o.y = fmaxf(a.y + bb.y + ind * cc.y, 0.f);
        o.z = fmaxf(b.x + bb.z + ind * cc.z, 0.f);
        o.w = fmaxf(b.y + bb.w + ind * cc.w, 0.f);
        *reinterpret_cast<float4*>(out + (size_t)nd * 64 + c) = o;
    }
}

// ---------------- layer 0: both views, shared base accumulator ----------------
__global__ void __launch_bounds__(256, 2) k_layer0(
    const float* __restrict__ nfeats, const float* __restrict__ hagg0,
    const float* __restrict__ efp, const float* __restrict__ efn,
    const float* __restrict__ bap, float* __restrict__ outp, float* __restrict__ outn, int n)
{
    extern __shared__ float sm[];
    float* Wsm = sm;
    float* Xs  = sm + 192 * 64;
    int tid = threadIdx.x;
    const float* Wc = d_Wc[0];
    #pragma unroll
    for (int t = tid; t < 192 * 64 / 4; t += 256)
        reinterpret_cast<float4*>(Wsm)[t] = reinterpret_cast<const float4*>(Wc)[t];

    int rowg = tid >> 2, colg = tid & 3;
    int cbase = colg << 2;
    int node0 = blockIdx.x * 64;
    int nd = node0 + rowg;

    u64 accB[8] = {0, 0, 0, 0, 0, 0, 0, 0};

    #pragma unroll
    for (int p = 0; p < 2; ++p) {
        const float* S = p ? hagg0 : nfeats;
        __syncthreads();
        stageX(Xs, S, node0, n, tid);
        __syncthreads();
        phase64(Xs, Wsm + p * 64 * 64, accB, rowg, cbase);
    }

    u64 acc[8];
    #pragma unroll
    for (int j = 0; j < 8; ++j) acc[j] = accB[j];
    __syncthreads();
    stageX(Xs, efp, node0, n, tid);
    __syncthreads();
    phase64(Xs, Wsm + 2 * 64 * 64, acc, rowg, cbase);
    epi_store(acc, bap, d_cv[0], outp, nd, cbase, n);

    #pragma unroll
    for (int j = 0; j < 8; ++j) acc[j] = accB[j];
    __syncthreads();
    stageX(Xs, efn, node0, n, tid);
    __syncthreads();
    phase64(Xs, Wsm + 2 * 64 * 64, acc, rowg, cbase);
    epi_store(acc, bap, d_cv[0], outn, nd, cbase, n);
}

// ---------------- layer 1: blockIdx.y = view, fused BCE reduction ----------------
__global__ void __launch_bounds__(256, 2) k_layer1(
    const float* __restrict__ h1p, const float* __restrict__ hp, const float* __restrict__ efp,
    const float* __restrict__ h1n, const float* __restrict__ hn, const float* __restrict__ efn,
    const float* __restrict__ bap, int n)
{
    extern __shared__ float sm[];
    float* Wsm = sm;
    float* Xs  = sm + 192 * 64;
    __shared__ float wred[8];
    int tid = threadIdx.x;
    const float* Wc = d_Wc[1];
    #pragma unroll
    for (int t = tid; t < 192 * 64 / 4; t += 256)
        reinterpret_cast<float4*>(Wsm)[t] = reinterpret_cast<const float4*>(Wc)[t];

    int rowg = tid >> 2, colg = tid & 3;
    int cbase = colg << 2;
    int node0 = blockIdx.x * 64;
    int view = blockIdx.y;
    const float* S0 = view ? h1n : h1p;
    const float* S1 = view ? hn  : hp;
    const float* S2 = view ? efn : efp;

    u64 acc[8] = {0, 0, 0, 0, 0, 0, 0, 0};

    #pragma unroll
    for (int p = 0; p < 3; ++p) {
        const float* S = (p == 0) ? S0 : (p == 1) ? S1 : S2;
        __syncthreads();
        stageX(Xs, S, node0, n, tid);
        __syncthreads();
        phase64(Xs, Wsm + p * 64 * 64, acc, rowg, cbase);
    }

    const float* cv = d_cv[1];
    float lsum = 0.f;
    int nd = node0 + rowg;
    if (nd < n) {
        float ind = (d_cnt[nd] > 0) ? 1.f : 0.f;
        #pragma unroll
        for (int m = 0; m < 4; ++m) {
            int c = cbase + (m << 4);
            float2 a = unpack2(acc[2 * m]);
            float2 b = unpack2(acc[2 * m + 1]);
            float4 bb = *reinterpret_cast<const float4*>(bap + c);
            float4 cc = *reinterpret_cast<const float4*>(cv + c);
            float xv[4];
            xv[0] = fmaxf(a.x + bb.x + ind * cc.x, 0.f);
            xv[1] = fmaxf(a.y + bb.y + ind * cc.y, 0.f);
            xv[2] = fmaxf(b.x + bb.z + ind * cc.z, 0.f);
            xv[3] = fmaxf(b.y + bb.w + ind * cc.w, 0.f);
            #pragma unroll
            for (int j = 0; j < 4; ++j) {
                float t = log1pf(expf(-xv[j]));
                lsum += view ? (xv[j] + t) : t;
            }
        }
    }
    int lane = tid & 31, wid = tid >> 5;
    #pragma unroll
    for (int o = 16; o; o >>= 1) lsum += __shfl_down_sync(~0u, lsum, o);
    if (lane == 0) wred[wid] = lsum;
    __syncthreads();
    if (tid < 8) {
        float s = wred[tid];
        #pragma unroll
        for (int o = 4; o; o >>= 1) s += __shfl_down_sync(0xffu, s, o);
        if (tid == 0) atomicAdd(&d_loss, (double)s);
    }
}

__global__ void k_write(float* out, double denom) {
    out[0] = (float)(d_loss / denom);
}

// ---------------- launch ----------------
extern "C" void kernel_launch(void* const* d_in, const int* in_sizes, int n_in,
                              void* d_out, int out_size) {
    const float* nfeats = (const float*)d_in[0];
    const float* efeats = (const float*)d_in[1];
    const int*   src    = (const int*)d_in[2];
    const int*   dst    = (const int*)d_in[3];
    const int*   perm   = (const int*)d_in[4];
    const float* Wm0 = (const float*)d_in[5];
    const float* bm0 = (const float*)d_in[6];
    const float* Wa0 = (const float*)d_in[7];
    const float* ba0 = (const float*)d_in[8];
    const float* Wm1 = (const float*)d_in[9];
    const float* bm1 = (const float*)d_in[10];
    const float* Wa1 = (const float*)d_in[11];
    const float* ba1 = (const float*)d_in[12];

    int n = in_sizes[0] / 64;
    int E = in_sizes[2];
    int nb = (n + 1023) / 1024;

    float *hagg0p, *efpp, *efnp, *h1pp, *h1np, *hpp, *hnp;
    cudaGetSymbolAddress((void**)&hagg0p, d_hagg0);
    cudaGetSymbolAddress((void**)&efpp,   d_efp);
    cudaGetSymbolAddress((void**)&efnp,   d_efn);
    cudaGetSymbolAddress((void**)&h1pp,   d_h1p);
    cudaGetSymbolAddress((void**)&h1np,   d_h1n);
    cudaGetSymbolAddress((void**)&hpp,    d_hp);
    cudaGetSymbolAddress((void**)&hnp,    d_hn);

    cudaFuncSetAttribute(k_layer0, cudaFuncAttributeMaxDynamicSharedMemorySize, LAYER_SMEM);
    cudaFuncSetAttribute(k_layer1, cudaFuncAttributeMaxDynamicSharedMemorySize, LAYER_SMEM);

    int gw = (n * 32 + 255) / 256;  // one warp per node
    int gl = (n + 63) / 64;         // 64 nodes per GEMM tile

    k_init   <<<(n + 255) / 256, 256>>>(n);
    k_hist   <<<(E + 255) / 256, 256>>>(dst, E);
    k_scan   <<<nb, 1024>>>(n, E, nb);
    k_scatter<<<(E + 255) / 256, 256>>>(src, dst, perm, E);
    k_agg3   <<<gw, 256>>>(nfeats, efeats, hagg0p, efpp, efnp, n);   // launch #5: profiled
    k_fold2  <<<2, 256>>>(Wm0, bm0, Wa0, Wm1, bm1, Wa1);
    k_layer0 <<<gl, 256, LAYER_SMEM>>>(nfeats, hagg0p, efpp, efnp, ba0, h1pp, h1np, n);
    k_aggh2  <<<gw, 256>>>(h1pp, h1np, hpp, hnp, n);
    {
        dim3 grid(gl, 2);
        k_layer1<<<grid, 256, LAYER_SMEM>>>(h1pp, hpp, efpp, h1np, hnp, efnp, ba1, n);
    }
    k_write<<<1, 1>>>((float*)d_out, (double)n * 64.0);
}

// round 4
// speedup vs baseline: 1.3181x; 1.3181x over previous
#include <cuda_runtime.h>
#include <math.h>

#define NN 100000
#define EE 1000000

// ---------------- device scratch ----------------
__device__ int    d_cnt[NN];
__device__ int    d_off[NN + 1];
__device__ int    d_cur[NN];
__device__ int    d_scan_tix;
__device__ unsigned long long d_scan_state[128];
__device__ int    d_eid[EE];
__device__ int    d_pid[EE];
__device__ int    d_ssrc[EE];
__device__ float  d_base [(size_t)NN * 64];
__device__ float  d_hagg0[(size_t)NN * 64];
__device__ float  d_efp [(size_t)NN * 64];
__device__ float  d_efn [(size_t)NN * 64];
__device__ float  d_h1p [(size_t)NN * 64];
__device__ float  d_h1n [(size_t)NN * 64];
__device__ float  d_hp  [(size_t)NN * 64];
__device__ float  d_hn  [(size_t)NN * 64];
__device__ float  d_Wc[2][192 * 64];
__device__ float  d_cv[2][64];
__device__ double d_loss;

typedef unsigned long long u64;

__device__ __forceinline__ u64 pack2(float x) {
    u64 r; asm("mov.b64 %0,{%1,%1};" : "=l"(r) : "f"(x)); return r;
}
__device__ __forceinline__ void fma2(u64& acc, u64 a, u64 b) {
    asm("fma.rn.f32x2 %0, %1, %2, %0;" : "+l"(acc) : "l"(a), "l"(b));
}
__device__ __forceinline__ float2 unpack2(u64 v) {
    float2 r; asm("mov.b64 {%0,%1},%2;" : "=f"(r.x), "=f"(r.y) : "l"(v)); return r;
}

// ---------------- fold Wmsg into Wapply (blockIdx = layer) ----------------
__global__ void k_fold2(const float* __restrict__ Wm0, const float* __restrict__ bm0,
                        const float* __restrict__ Wa0,
                        const float* __restrict__ Wm1, const float* __restrict__ bm1,
                        const float* __restrict__ Wa1) {
    int layer = blockIdx.x;
    const float* Wmsg = layer ? Wm1 : Wm0;
    const float* bmsg = layer ? bm1 : bm0;
    const float* Wap  = layer ? Wa1 : Wa0;
    __shared__ float Wn[64][64];
    __shared__ float bm[64];
    int tid = threadIdx.x;
    for (int idx = tid; idx < 64 * 64; idx += 256) {
        int j = idx >> 6, t = idx & 63;
        Wn[t][j] = Wap[j * 128 + 64 + t];
    }
    if (tid < 64) bm[tid] = bmsg[tid];
    __syncthreads();
    for (int idx = tid; idx < 192 * 64; idx += 256) {
        int k = idx >> 6, j = idx & 63;
        float r;
        if (k < 64) {
            r = Wap[j * 128 + k];
        } else {
            int col = k - 64;
            float a = 0.f;
            #pragma unroll
            for (int t = 0; t < 64; ++t) a += Wmsg[t * 128 + col] * Wn[t][j];
            r = a;
        }
        d_Wc[layer][k * 64 + j] = r;
    }
    for (int j = tid; j < 64; j += 256) {
        float a = 0.f;
        #pragma unroll
        for (int t = 0; t < 64; ++t) a += bm[t] * Wn[t][j];
        d_cv[layer][j] = a;
    }
}

// ---------------- init / CSR build ----------------
__global__ void k_init(int n) {
    int i = blockIdx.x * blockDim.x + threadIdx.x;
    if (i < n) { d_cnt[i] = 0; d_cur[i] = 0; }
    if (i < 128) d_scan_state[i] = 0ULL;
    if (i == 0) { d_loss = 0.0; d_scan_tix = 0; }
}

__global__ void k_hist(const int* __restrict__ dst, int E) {
    int e = blockIdx.x * blockDim.x + threadIdx.x;
    if (e < E) atomicAdd(&d_cnt[dst[e]], 1);
}

__global__ void k_scan(int n, int E, int nb) {
    __shared__ int ws[32];
    __shared__ int s_bid;
    __shared__ int s_pref;
    if (threadIdx.x == 0) s_bid = atomicAdd(&d_scan_tix, 1);
    __syncthreads();
    int bid = s_bid;
    int i = bid * 1024 + threadIdx.x;
    int lane = threadIdx.x & 31, wid = threadIdx.x >> 5;
    int v = (i < n) ? d_cnt[i] : 0;
    int x = v;
    #pragma unroll
    for (int o = 1; o < 32; o <<= 1) { int y = __shfl_up_sync(~0u, x, o); if (lane >= o) x += y; }
    if (lane == 31) ws[wid] = x;
    __syncthreads();
    if (wid == 0) {
        int w = ws[lane];
        #pragma unroll
        for (int o = 1; o < 32; o <<= 1) { int y = __shfl_up_sync(~0u, w, o); if (lane >= o) w += y; }
        ws[lane] = w;
    }
    __syncthreads();
    int incl = x + (wid > 0 ? ws[wid - 1] : 0);
    int total = ws[31];

    if (threadIdx.x == 0) {
        if (bid == 0) {
            atomicExch(&d_scan_state[0], (2ULL << 32) | (unsigned)total);
            s_pref = 0;
        } else {
            atomicExch(&d_scan_state[bid], (1ULL << 32) | (unsigned)total);
            int pref = 0;
            for (int j = bid - 1; j >= 0; --j) {
                unsigned long long st;
                do { st = atomicAdd(&d_scan_state[j], 0ULL); } while (!(st >> 32));
                pref += (int)(unsigned)st;
                if ((st >> 32) == 2ULL) break;
            }
            atomicExch(&d_scan_state[bid], (2ULL << 32) | (unsigned)(pref + total));
            s_pref = pref;
        }
    }
    __syncthreads();
    int pref = s_pref;
    if (i < n) d_off[i] = pref + incl - v;
    if (bid == nb - 1 && threadIdx.x == 0) d_off[n] = E;
}

__global__ void k_scatter(const int* __restrict__ src, const int* __restrict__ dst,
                          const int* __restrict__ perm, int E) {
    int e = blockIdx.x * blockDim.x + threadIdx.x;
    if (e < E) {
        int d = dst[e];
        int p = d_off[d] + atomicAdd(&d_cur[d], 1);
        d_eid[p]  = e;
        d_pid[p]  = perm[e];
        d_ssrc[p] = src[e];
    }
}

// ---------------- fused first-stage aggregation ----------------
__global__ void k_agg3(const float* __restrict__ nfeats, const float* __restrict__ ef,
                       float* __restrict__ hagg0, float* __restrict__ efp,
                       float* __restrict__ efn, int n) {
    int gw = (blockIdx.x * blockDim.x + threadIdx.x) >> 5;
    int lane = threadIdx.x & 31;
    if (gw >= n) return;
    int beg = d_off[gw], end = d_off[gw + 1];
    int half = lane >> 4;
    int c4 = (lane & 15) << 2;
    float4 ah = make_float4(0.f, 0.f, 0.f, 0.f);
    float4 ap = ah, an = ah;
    for (int k = beg + half; k < end; k += 2) {
        int s  = __ldg(&d_ssrc[k]);
        int e  = __ldg(&d_eid[k]);
        int pe = __ldg(&d_pid[k]);
        float4 v1 = *reinterpret_cast<const float4*>(nfeats + (size_t)s  * 64 + c4);
        float4 v2 = *reinterpret_cast<const float4*>(ef     + (size_t)e  * 64 + c4);
        float4 v3 = *reinterpret_cast<const float4*>(ef     + (size_t)pe * 64 + c4);
        ah.x += v1.x; ah.y += v1.y; ah.z += v1.z; ah.w += v1.w;
        ap.x += v2.x; ap.y += v2.y; ap.z += v2.z; ap.w += v2.w;
        an.x += v3.x; an.y += v3.y; an.z += v3.z; an.w += v3.w;
    }
    ah.x += __shfl_xor_sync(~0u, ah.x, 16); ah.y += __shfl_xor_sync(~0u, ah.y, 16);
    ah.z += __shfl_xor_sync(~0u, ah.z, 16); ah.w += __shfl_xor_sync(~0u, ah.w, 16);
    ap.x += __shfl_xor_sync(~0u, ap.x, 16); ap.y += __shfl_xor_sync(~0u, ap.y, 16);
    ap.z += __shfl_xor_sync(~0u, ap.z, 16); ap.w += __shfl_xor_sync(~0u, ap.w, 16);
    an.x += __shfl_xor_sync(~0u, an.x, 16); an.y += __shfl_xor_sync(~0u, an.y, 16);
    an.z += __shfl_xor_sync(~0u, an.z, 16); an.w += __shfl_xor_sync(~0u, an.w, 16);
    float inv = 1.f / fmaxf((float)(end - beg), 1.f);
    if (half == 0) {
        *reinterpret_cast<float4*>(hagg0 + (size_t)gw * 64 + c4) =
            make_float4(ah.x * inv, ah.y * inv, ah.z * inv, ah.w * inv);
        *reinterpret_cast<float4*>(efp + (size_t)gw * 64 + c4) =
            make_float4(ap.x * inv, ap.y * inv, ap.z * inv, ap.w * inv);
        *reinterpret_cast<float4*>(efn + (size_t)gw * 64 + c4) =
            make_float4(an.x * inv, an.y * inv, an.z * inv, an.w * inv);
    }
}

// ---------------- second-stage aggregation: hp + hn ----------------
__global__ void k_aggh2(const float* __restrict__ fa, const float* __restrict__ fb,
                        float* __restrict__ oa, float* __restrict__ ob, int n) {
    int gw = (blockIdx.x * blockDim.x + threadIdx.x) >> 5;
    int lane = threadIdx.x & 31;
    if (gw >= n) return;
    int beg = d_off[gw], end = d_off[gw + 1];
    int half = lane >> 4;
    int c4 = (lane & 15) << 2;
    float4 aa = make_float4(0.f, 0.f, 0.f, 0.f);
    float4 ab = aa;
    for (int k = beg + half; k < end; k += 2) {
        int s = __ldg(&d_ssrc[k]);
        float4 v1 = *reinterpret_cast<const float4*>(fa + (size_t)s * 64 + c4);
        float4 v2 = *reinterpret_cast<const float4*>(fb + (size_t)s * 64 + c4);
        aa.x += v1.x; aa.y += v1.y; aa.z += v1.z; aa.w += v1.w;
        ab.x += v2.x; ab.y += v2.y; ab.z += v2.z; ab.w += v2.w;
    }
    aa.x += __shfl_xor_sync(~0u, aa.x, 16); aa.y += __shfl_xor_sync(~0u, aa.y, 16);
    aa.z += __shfl_xor_sync(~0u, aa.z, 16); aa.w += __shfl_xor_sync(~0u, aa.w, 16);
    ab.x += __shfl_xor_sync(~0u, ab.x, 16); ab.y += __shfl_xor_sync(~0u, ab.y, 16);
    ab.z += __shfl_xor_sync(~0u, ab.z, 16); ab.w += __shfl_xor_sync(~0u, ab.w, 16);
    float inv = 1.f / fmaxf((float)(end - beg), 1.f);
    if (half == 0) {
        *reinterpret_cast<float4*>(oa + (size_t)gw * 64 + c4) =
            make_float4(aa.x * inv, aa.y * inv, aa.z * inv, aa.w * inv);
        *reinterpret_cast<float4*>(ob + (size_t)gw * 64 + c4) =
            make_float4(ab.x * inv, ab.y * inv, ab.z * inv, ab.w * inv);
    }
}

// ---------------- GEMM building blocks ----------------
// Tile: 128 rows x 64 cols, 256 threads. rowg = tid>>2 (2 rows), colg = tid&3,
// cols { colg*4 + 16m + 0..3 } -> acc u64[2][8].
// Smem: Xs[128][66] (33.8KB) + Ws[64][64] (16KB), dynamic.

#define XS 66
#define GEMM_SMEM ((128 * XS + 64 * 64) * 4)

__device__ __forceinline__ void stageX(float (*Xs)[XS], const float* __restrict__ S,
                                       int node0, int n, int tid) {
    #pragma unroll
    for (int it = 0; it < 8; ++it) {
        int t = tid + it * 256;
        int r = t >> 4, c4 = (t & 15) << 2;
        int nd = node0 + r;
        float4 v = make_float4(0.f, 0.f, 0.f, 0.f);
        if (nd < n) v = *reinterpret_cast<const float4*>(S + (size_t)nd * 64 + c4);
        *reinterpret_cast<float2*>(&Xs[r][c4])     = make_float2(v.x, v.y);
        *reinterpret_cast<float2*>(&Xs[r][c4 + 2]) = make_float2(v.z, v.w);
    }
}

__device__ __forceinline__ void stageW(float (*Ws)[64], const float* __restrict__ Wg, int tid) {
    #pragma unroll
    for (int it = 0; it < 4; ++it) {
        int t = tid + it * 256;
        reinterpret_cast<float4*>(&Ws[0][0])[t] = reinterpret_cast<const float4*>(Wg)[t];
    }
}

__device__ __forceinline__ void panel64(const float (*Xs)[XS], const float (*Ws)[64],
                                        u64 acc[2][8], int r0, int cbase) {
    #pragma unroll 8
    for (int k = 0; k < 64; ++k) {
        u64 x0 = pack2(Xs[r0][k]);
        u64 x1 = pack2(Xs[r0 + 1][k]);
        const float* wr = &Ws[k][cbase];
        ulonglong2 w0 = *reinterpret_cast<const ulonglong2*>(wr);
        ulonglong2 w1 = *reinterpret_cast<const ulonglong2*>(wr + 16);
        ulonglong2 w2 = *reinterpret_cast<const ulonglong2*>(wr + 32);
        ulonglong2 w3 = *reinterpret_cast<const ulonglong2*>(wr + 48);
        fma2(acc[0][0], x0, w0.x); fma2(acc[0][1], x0, w0.y);
        fma2(acc[0][2], x0, w1.x); fma2(acc[0][3], x0, w1.y);
        fma2(acc[0][4], x0, w2.x); fma2(acc[0][5], x0, w2.y);
        fma2(acc[0][6], x0, w3.x); fma2(acc[0][7], x0, w3.y);
        fma2(acc[1][0], x1, w0.x); fma2(acc[1][1], x1, w0.y);
        fma2(acc[1][2], x1, w1.x); fma2(acc[1][3], x1, w1.y);
        fma2(acc[1][4], x1, w2.x); fma2(acc[1][5], x1, w2.y);
        fma2(acc[1][6], x1, w3.x); fma2(acc[1][7], x1, w3.y);
    }
}

__device__ __forceinline__ void epi_store(const u64 acc[2][8], const float* __restrict__ bap,
                                          const float* __restrict__ cv, float* __restrict__ out,
                                          int node0, int r0, int cbase, int n) {
    #pragma unroll
    for (int i = 0; i < 2; ++i) {
        int nd = node0 + r0 + i;
        if (nd >= n) break;
        float ind = (d_cnt[nd] > 0) ? 1.f : 0.f;
        #pragma unroll
        for (int m = 0; m < 4; ++m) {
            int c = cbase + (m << 4);
            float2 a = unpack2(acc[i][2 * m]);
            float2 b = unpack2(acc[i][2 * m + 1]);
            float4 bb = *reinterpret_cast<const float4*>(bap + c);
            float4 cc = *reinterpret_cast<const float4*>(cv + c);
            float4 o;
            o.x = fmaxf(a.x + bb.x + ind * cc.x, 0.f);
            o.y = fmaxf(a.y + bb.y + ind * cc.y, 0.f);
            o.z = fmaxf(b.x + bb.z + ind * cc.z, 0.f);
            o.w = fmaxf(b.y + bb.w + ind * cc.w, 0.f);
            *reinterpret_cast<float4*>(out + (size_t)nd * 64 + c) = o;
        }
    }
}

// ---------------- pure base GEMM: d_base = nfeats @ Wc0[0:64] (profiled slot) ----------------
__global__ void __launch_bounds__(256) k_base(const float* __restrict__ nfeats, int n) {
    extern __shared__ float sm[];
    float (*Xs)[XS] = reinterpret_cast<float(*)[XS]>(sm);
    float (*Ws)[64] = reinterpret_cast<float(*)[64]>(sm + 128 * XS);
    int tid = threadIdx.x;
    int rowg = tid >> 2, colg = tid & 3;
    int r0 = rowg * 2, cbase = colg << 2;
    int node0 = blockIdx.x * 128;

    stageX(Xs, nfeats, node0, n, tid);
    stageW(Ws, d_Wc[0], tid);
    __syncthreads();

    u64 acc[2][8] = {{0}};
    panel64(Xs, Ws, acc, r0, cbase);

    #pragma unroll
    for (int i = 0; i < 2; ++i) {
        int nd = node0 + r0 + i;
        if (nd >= n) break;
        #pragma unroll
        for (int m = 0; m < 4; ++m) {
            int c = cbase + (m << 4);
            float2 a = unpack2(acc[i][2 * m]);
            float2 b = unpack2(acc[i][2 * m + 1]);
            *reinterpret_cast<float4*>(d_base + (size_t)nd * 64 + c) =
                make_float4(a.x, a.y, b.x, b.y);
        }
    }
}

// ---------------- layer 0: base + hagg0 shared, two ef tails ----------------
__global__ void __launch_bounds__(256) k_layer0(
    const float* __restrict__ hagg0, const float* __restrict__ efp,
    const float* __restrict__ efn, const float* __restrict__ bap,
    float* __restrict__ outp, float* __restrict__ outn, int n)
{
    extern __shared__ float sm[];
    float (*Xs)[XS] = reinterpret_cast<float(*)[XS]>(sm);
    float (*Ws)[64] = reinterpret_cast<float(*)[64]>(sm + 128 * XS);
    int tid = threadIdx.x;
    int rowg = tid >> 2, colg = tid & 3;
    int r0 = rowg * 2, cbase = colg << 2;
    int node0 = blockIdx.x * 128;
    const float* Wc = d_Wc[0];

    // accB init from precomputed base
    u64 accB[2][8];
    #pragma unroll
    for (int i = 0; i < 2; ++i) {
        int nd = node0 + r0 + i;
        #pragma unroll
        for (int m = 0; m < 4; ++m) {
            float4 v = make_float4(0.f, 0.f, 0.f, 0.f);
            if (nd < n) v = *reinterpret_cast<const float4*>(d_base + (size_t)nd * 64 + cbase + (m << 4));
            accB[i][2 * m]     = pack2(0.f);
            accB[i][2 * m + 1] = pack2(0.f);
            float2 t0 = make_float2(v.x, v.y), t1 = make_float2(v.z, v.w);
            asm("mov.b64 %0,{%1,%2};" : "=l"(accB[i][2 * m])     : "f"(t0.x), "f"(t0.y));
            asm("mov.b64 %0,{%1,%2};" : "=l"(accB[i][2 * m + 1]) : "f"(t1.x), "f"(t1.y));
        }
    }

    // hagg0 phase (W rows 64..127)
    stageX(Xs, hagg0, node0, n, tid);
    stageW(Ws, Wc + 64 * 64, tid);
    __syncthreads();
    panel64(Xs, Ws, accB, r0, cbase);
    __syncthreads();

    // positive ef tail (W rows 128..191)
    stageX(Xs, efp, node0, n, tid);
    stageW(Ws, Wc + 128 * 64, tid);
    __syncthreads();
    u64 acc[2][8];
    #pragma unroll
    for (int i = 0; i < 2; ++i)
        #pragma unroll
        for (int j = 0; j < 8; ++j) acc[i][j] = accB[i][j];
    panel64(Xs, Ws, acc, r0, cbase);
    epi_store(acc, bap, d_cv[0], outp, node0, r0, cbase, n);
    __syncthreads();

    // negative ef tail (same W panel stays resident)
    stageX(Xs, efn, node0, n, tid);
    __syncthreads();
    #pragma unroll
    for (int i = 0; i < 2; ++i)
        #pragma unroll
        for (int j = 0; j < 8; ++j) acc[i][j] = accB[i][j];
    panel64(Xs, Ws, acc, r0, cbase);
    epi_store(acc, bap, d_cv[0], outn, node0, r0, cbase, n);
}

// ---------------- layer 1: blockIdx.y = view, fused BCE reduction ----------------
__global__ void __launch_bounds__(256) k_layer1(
    const float* __restrict__ h1p, const float* __restrict__ hp, const float* __restrict__ efp,
    const float* __restrict__ h1n, const float* __restrict__ hn, const float* __restrict__ efn,
    const float* __restrict__ bap, int n)
{
    extern __shared__ float sm[];
    float (*Xs)[XS] = reinterpret_cast<float(*)[XS]>(sm);
    float (*Ws)[64] = reinterpret_cast<float(*)[64]>(sm + 128 * XS);
    __shared__ float wred[8];
    int tid = threadIdx.x;
    int rowg = tid >> 2, colg = tid & 3;
    int r0 = rowg * 2, cbase = colg << 2;
    int node0 = blockIdx.x * 128;
    int view = blockIdx.y;
    const float* Wc = d_Wc[1];
    const float* S0 = view ? h1n : h1p;
    const float* S1 = view ? hn  : hp;
    const float* S2 = view ? efn : efp;

    u64 acc[2][8] = {{0}};

    #pragma unroll
    for (int p = 0; p < 3; ++p) {
        const float* S = (p == 0) ? S0 : (p == 1) ? S1 : S2;
        if (p) __syncthreads();
        stageX(Xs, S, node0, n, tid);
        stageW(Ws, Wc + p * 64 * 64, tid);
        __syncthreads();
        panel64(Xs, Ws, acc, r0, cbase);
    }

    const float* cv = d_cv[1];
    float lsum = 0.f;
    #pragma unroll
    for (int i = 0; i < 2; ++i) {
        int nd = node0 + r0 + i;
        if (nd < n) {
            float ind = (d_cnt[nd] > 0) ? 1.f : 0.f;
            #pragma unroll
            for (int m = 0; m < 4; ++m) {
                int c = cbase + (m << 4);
                float2 a = unpack2(acc[i][2 * m]);
                float2 b = unpack2(acc[i][2 * m + 1]);
                float4 bb = *reinterpret_cast<const float4*>(bap + c);
                float4 cc = *reinterpret_cast<const float4*>(cv + c);
                float xv[4];
                xv[0] = fmaxf(a.x + bb.x + ind * cc.x, 0.f);
                xv[1] = fmaxf(a.y + bb.y + ind * cc.y, 0.f);
                xv[2] = fmaxf(b.x + bb.z + ind * cc.z, 0.f);
                xv[3] = fmaxf(b.y + bb.w + ind * cc.w, 0.f);
                #pragma unroll
                for (int j = 0; j < 4; ++j) {
                    float t = log1pf(expf(-xv[j]));
                    lsum += view ? (xv[j] + t) : t;
                }
            }
        }
    }
    int lane = tid & 31, wid = tid >> 5;
    #pragma unroll
    for (int o = 16; o; o >>= 1) lsum += __shfl_down_sync(~0u, lsum, o);
    if (lane == 0) wred[wid] = lsum;
    __syncthreads();
    if (tid < 8) {
        float s = wred[tid];
        #pragma unroll
        for (int o = 4; o; o >>= 1) s += __shfl_down_sync(0xffu, s, o);
        if (tid == 0) atomicAdd(&d_loss, (double)s);
    }
}

__global__ void k_write(float* out, double denom) {
    out[0] = (float)(d_loss / denom);
}

// ---------------- launch ----------------
extern "C" void kernel_launch(void* const* d_in, const int* in_sizes, int n_in,
                              void* d_out, int out_size) {
    const float* nfeats = (const float*)d_in[0];
    const float* efeats = (const float*)d_in[1];
    const int*   src    = (const int*)d_in[2];
    const int*   dst    = (const int*)d_in[3];
    const int*   perm   = (const int*)d_in[4];
    const float* Wm0 = (const float*)d_in[5];
    const float* bm0 = (const float*)d_in[6];
    const float* Wa0 = (const float*)d_in[7];
    const float* ba0 = (const float*)d_in[8];
    const float* Wm1 = (const float*)d_in[9];
    const float* bm1 = (const float*)d_in[10];
    const float* Wa1 = (const float*)d_in[11];
    const float* ba1 = (const float*)d_in[12];

    int n = in_sizes[0] / 64;
    int E = in_sizes[2];
    int nb = (n + 1023) / 1024;

    float *hagg0p, *efpp, *efnp, *h1pp, *h1np, *hpp, *hnp;
    cudaGetSymbolAddress((void**)&hagg0p, d_hagg0);
    cudaGetSymbolAddress((void**)&efpp,   d_efp);
    cudaGetSymbolAddress((void**)&efnp,   d_efn);
    cudaGetSymbolAddress((void**)&h1pp,   d_h1p);
    cudaGetSymbolAddress((void**)&h1np,   d_h1n);
    cudaGetSymbolAddress((void**)&hpp,    d_hp);
    cudaGetSymbolAddress((void**)&hnp,    d_hn);

    cudaFuncSetAttribute(k_base,   cudaFuncAttributeMaxDynamicSharedMemorySize, GEMM_SMEM);
    cudaFuncSetAttribute(k_layer0, cudaFuncAttributeMaxDynamicSharedMemorySize, GEMM_SMEM);
    cudaFuncSetAttribute(k_layer1, cudaFuncAttributeMaxDynamicSharedMemorySize, GEMM_SMEM);

    int gw = (n * 32 + 255) / 256;  // one warp per node
    int gl = (n + 127) / 128;       // 128 nodes per GEMM tile

    k_fold2  <<<2, 256>>>(Wm0, bm0, Wa0, Wm1, bm1, Wa1);     // 1
    k_init   <<<(n + 255) / 256, 256>>>(n);                  // 2
    k_hist   <<<(E + 255) / 256, 256>>>(dst, E);             // 3
    k_base   <<<gl, 256, GEMM_SMEM>>>(nfeats, n);            // 4  <- profiled
    k_scan   <<<nb, 1024>>>(n, E, nb);                       // 5
    k_scatter<<<(E + 255) / 256, 256>>>(src, dst, perm, E);  // 6
    k_agg3   <<<gw, 256>>>(nfeats, efeats, hagg0p, efpp, efnp, n);          // 7
    k_layer0 <<<gl, 256, GEMM_SMEM>>>(hagg0p, efpp, efnp, ba0, h1pp, h1np, n); // 8
    k_aggh2  <<<gw, 256>>>(h1pp, h1np, hpp, hnp, n);         // 9
    {
        dim3 grid(gl, 2);
        k_layer1<<<grid, 256, GEMM_SMEM>>>(h1pp, hpp, efpp, h1np, hnp, efnp, ba1, n); // 10
    }
    k_write<<<1, 1>>>((float*)d_out, (double)n * 64.0);      // 11
}

// round 6
// speedup vs baseline: 2.0051x; 1.5212x over previous
#include <cuda_runtime.h>
#include <cuda_bf16.h>
#include <math.h>
#include <cstdint>

#define NN 100000
#define EE 1000000

// ---------------- device scratch ----------------
__device__ int    d_cnt[NN];
__device__ int    d_off[NN + 1];
__device__ int    d_cur[NN];
__device__ int    d_scan_tix;
__device__ unsigned long long d_scan_state[128];
__device__ int    d_eid[EE];
__device__ int    d_pid[EE];
__device__ int    d_ssrc[EE];
__device__ __nv_bfloat16 d_hagg0[(size_t)NN * 64];
__device__ __nv_bfloat16 d_efp [(size_t)NN * 64];
__device__ __nv_bfloat16 d_efn [(size_t)NN * 64];
__device__ __nv_bfloat16 d_h1p [(size_t)NN * 64];
__device__ __nv_bfloat16 d_h1n [(size_t)NN * 64];
__device__ __nv_bfloat16 d_hp  [(size_t)NN * 64];
__device__ __nv_bfloat16 d_hn  [(size_t)NN * 64];
// folded W in tf32, stored in exact mma B-fragment order:
// idx = ((panel*8 + s)*8 + nb)*64 + t*2 + slot
__device__ float  d_Wf[2][3 * 8 * 8 * 64];
__device__ float  d_cv[2][64];
__device__ double d_loss;

// ---------------- helpers ----------------
__device__ __forceinline__ float tf32r(float x) {
    uint32_t r; asm("cvt.rna.tf32.f32 %0, %1;" : "=r"(r) : "f"(x));
    return __uint_as_float(r);
}
__device__ __forceinline__ void mma_tf32(float* c, uint32_t a0, uint32_t a1, uint32_t a2, uint32_t a3,
                                         uint32_t b0, uint32_t b1) {
    asm volatile("mma.sync.aligned.m16n8k8.row.col.f32.tf32.tf32.f32 "
                 "{%0,%1,%2,%3}, {%4,%5,%6,%7}, {%8,%9}, {%0,%1,%2,%3};"
                 : "+f"(c[0]), "+f"(c[1]), "+f"(c[2]), "+f"(c[3])
                 : "r"(a0), "r"(a1), "r"(a2), "r"(a3), "r"(b0), "r"(b1));
}
__device__ __forceinline__ uint32_t bf2(float x, float y) {
    uint32_t r; asm("cvt.rn.satfinite.bf16x2.f32 %0, %1, %2;" : "=r"(r) : "f"(y), "f"(x)); return r;
}
__device__ __forceinline__ float2 bf2f(uint32_t v) {
    __nv_bfloat162 h = *reinterpret_cast<__nv_bfloat162*>(&v);
    return __bfloat1622float2(h);
}

// ---------------- init / CSR build ----------------
__global__ void k_init(int n) {
    int i = blockIdx.x * blockDim.x + threadIdx.x;
    if (i < n) { d_cnt[i] = 0; d_cur[i] = 0; }
    if (i < 128) d_scan_state[i] = 0ULL;
    if (i == 0) { d_loss = 0.0; d_scan_tix = 0; }
}

__global__ void k_hist(const int* __restrict__ dst, int E) {
    int e = blockIdx.x * blockDim.x + threadIdx.x;
    if (e < E) atomicAdd(&d_cnt[dst[e]], 1);
}

__global__ void k_scan(int n, int E, int nb) {
    __shared__ int ws[32];
    __shared__ int s_bid;
    __shared__ int s_pref;
    if (threadIdx.x == 0) s_bid = atomicAdd(&d_scan_tix, 1);
    __syncthreads();
    int bid = s_bid;
    int i = bid * 1024 + threadIdx.x;
    int lane = threadIdx.x & 31, wid = threadIdx.x >> 5;
    int v = (i < n) ? d_cnt[i] : 0;
    int x = v;
    #pragma unroll
    for (int o = 1; o < 32; o <<= 1) { int y = __shfl_up_sync(~0u, x, o); if (lane >= o) x += y; }
    if (lane == 31) ws[wid] = x;
    __syncthreads();
    if (wid == 0) {
        int w = ws[lane];
        #pragma unroll
        for (int o = 1; o < 32; o <<= 1) { int y = __shfl_up_sync(~0u, w, o); if (lane >= o) w += y; }
        ws[lane] = w;
    }
    __syncthreads();
    int incl = x + (wid > 0 ? ws[wid - 1] : 0);
    int total = ws[31];
    if (threadIdx.x == 0) {
        if (bid == 0) {
            atomicExch(&d_scan_state[0], (2ULL << 32) | (unsigned)total);
            s_pref = 0;
        } else {
            atomicExch(&d_scan_state[bid], (1ULL << 32) | (unsigned)total);
            int pref = 0;
            for (int j = bid - 1; j >= 0; --j) {
                unsigned long long st;
                do { st = atomicAdd(&d_scan_state[j], 0ULL); } while (!(st >> 32));
                pref += (int)(unsigned)st;
                if ((st >> 32) == 2ULL) break;
            }
            atomicExch(&d_scan_state[bid], (2ULL << 32) | (unsigned)(pref + total));
            s_pref = pref;
        }
    }
    __syncthreads();
    int pref = s_pref;
    if (i < n) d_off[i] = pref + incl - v;
    if (bid == nb - 1 && threadIdx.x == 0) d_off[n] = E;
}

__global__ void k_scatter(const int* __restrict__ src, const int* __restrict__ dst,
                          const int* __restrict__ perm, int E) {
    int e = blockIdx.x * blockDim.x + threadIdx.x;
    if (e < E) {
        int d = dst[e];
        int p = d_off[d] + atomicAdd(&d_cur[d], 1);
        d_eid[p]  = e;
        d_pid[p]  = perm[e];
        d_ssrc[p] = src[e];
    }
}

// ---------------- fold Wmsg into Wapply -> tf32 B-fragment layout ----------------
__global__ void k_fold2(const float* __restrict__ Wm0, const float* __restrict__ bm0,
                        const float* __restrict__ Wa0,
                        const float* __restrict__ Wm1, const float* __restrict__ bm1,
                        const float* __restrict__ Wa1) {
    int layer = blockIdx.x;
    const float* Wmsg = layer ? Wm1 : Wm0;
    const float* bmsg = layer ? bm1 : bm0;
    const float* Wap  = layer ? Wa1 : Wa0;
    __shared__ float Wn[64][64];
    __shared__ float bm[64];
    int tid = threadIdx.x;
    for (int idx = tid; idx < 64 * 64; idx += 256) {
        int j = idx >> 6, t = idx & 63;
        Wn[t][j] = Wap[j * 128 + 64 + t];
    }
    if (tid < 64) bm[tid] = bmsg[tid];
    __syncthreads();
    for (int idx = tid; idx < 192 * 64; idx += 256) {
        int k = idx >> 6, j = idx & 63;
        float r;
        if (k < 64) {
            r = Wap[j * 128 + k];
        } else {
            int col = k - 64;
            float a = 0.f;
            #pragma unroll
            for (int t = 0; t < 64; ++t) a += Wmsg[t * 128 + col] * Wn[t][j];
            r = a;
        }
        // B-fragment placement: b_slot = W[k in {base, base+4}], n = j
        int panel = k >> 6, kk = k & 63;
        int s = kk >> 3, krem = kk & 7;
        int slot = krem >> 2, kq = krem & 3;
        int t = ((j & 7) << 2) | kq;
        int nb = j >> 3;
        int o = ((panel * 8 + s) * 8 + nb) * 64 + t * 2 + slot;
        d_Wf[layer][o] = tf32r(r);
    }
    for (int j = tid; j < 64; j += 256) {
        float a = 0.f;
        #pragma unroll
        for (int t = 0; t < 64; ++t) a += bm[t] * Wn[t][j];
        d_cv[layer][j] = a;
    }
}

// ---------------- fused first-stage aggregation (fp32 in, bf16 out) ----------------
__global__ void k_agg3(const float* __restrict__ nf, const float* __restrict__ ef, int n) {
    int gw = (blockIdx.x * blockDim.x + threadIdx.x) >> 5;
    int lane = threadIdx.x & 31;
    if (gw >= n) return;
    int beg = d_off[gw], end = d_off[gw + 1];
    int half = lane >> 4;
    int c = lane & 15;
    float4 ah = make_float4(0.f, 0.f, 0.f, 0.f);
    float4 ap = ah, an = ah;
    for (int k = beg + half; k < end; k += 2) {
        int s  = __ldg(&d_ssrc[k]);
        int e  = __ldg(&d_eid[k]);
        int pe = __ldg(&d_pid[k]);
        float4 v1 = __ldg((const float4*)nf + (size_t)s  * 16 + c);
        float4 v2 = __ldg((const float4*)ef + (size_t)e  * 16 + c);
        float4 v3 = __ldg((const float4*)ef + (size_t)pe * 16 + c);
        ah.x += v1.x; ah.y += v1.y; ah.z += v1.z; ah.w += v1.w;
        ap.x += v2.x; ap.y += v2.y; ap.z += v2.z; ap.w += v2.w;
        an.x += v3.x; an.y += v3.y; an.z += v3.z; an.w += v3.w;
    }
    ah.x += __shfl_xor_sync(~0u, ah.x, 16); ah.y += __shfl_xor_sync(~0u, ah.y, 16);
    ah.z += __shfl_xor_sync(~0u, ah.z, 16); ah.w += __shfl_xor_sync(~0u, ah.w, 16);
    ap.x += __shfl_xor_sync(~0u, ap.x, 16); ap.y += __shfl_xor_sync(~0u, ap.y, 16);
    ap.z += __shfl_xor_sync(~0u, ap.z, 16); ap.w += __shfl_xor_sync(~0u, ap.w, 16);
    an.x += __shfl_xor_sync(~0u, an.x, 16); an.y += __shfl_xor_sync(~0u, an.y, 16);
    an.z += __shfl_xor_sync(~0u, an.z, 16); an.w += __shfl_xor_sync(~0u, an.w, 16);
    if (half == 0) {
        float inv = 1.f / fmaxf((float)(end - beg), 1.f);
        uint2 o;
        o.x = bf2(ah.x * inv, ah.y * inv); o.y = bf2(ah.z * inv, ah.w * inv);
        reinterpret_cast<uint2*>(d_hagg0)[(size_t)gw * 16 + c] = o;
        o.x = bf2(ap.x * inv, ap.y * inv); o.y = bf2(ap.z * inv, ap.w * inv);
        reinterpret_cast<uint2*>(d_efp)[(size_t)gw * 16 + c] = o;
        o.x = bf2(an.x * inv, an.y * inv); o.y = bf2(an.z * inv, an.w * inv);
        reinterpret_cast<uint2*>(d_efn)[(size_t)gw * 16 + c] = o;
    }
}

// ---------------- second-stage aggregation: hp + hn (bf16 in/out) ----------------
__global__ void k_aggh2(int n) {
    int gw = (blockIdx.x * blockDim.x + threadIdx.x) >> 5;
    int lane = threadIdx.x & 31;
    if (gw >= n) return;
    int beg = d_off[gw], end = d_off[gw + 1];
    int half = lane >> 4;
    int c = lane & 15;
    float4 aa = make_float4(0.f, 0.f, 0.f, 0.f);
    float4 ab = aa;
    const uint2* fa = reinterpret_cast<const uint2*>(d_h1p);
    const uint2* fb = reinterpret_cast<const uint2*>(d_h1n);
    for (int k = beg + half; k < end; k += 2) {
        int s = __ldg(&d_ssrc[k]);
        uint2 v1 = __ldg(fa + (size_t)s * 16 + c);
        uint2 v2 = __ldg(fb + (size_t)s * 16 + c);
        float2 a0 = bf2f(v1.x), a1 = bf2f(v1.y);
        float2 b0 = bf2f(v2.x), b1 = bf2f(v2.y);
        aa.x += a0.x; aa.y += a0.y; aa.z += a1.x; aa.w += a1.y;
        ab.x += b0.x; ab.y += b0.y; ab.z += b1.x; ab.w += b1.y;
    }
    aa.x += __shfl_xor_sync(~0u, aa.x, 16); aa.y += __shfl_xor_sync(~0u, aa.y, 16);
    aa.z += __shfl_xor_sync(~0u, aa.z, 16); aa.w += __shfl_xor_sync(~0u, aa.w, 16);
    ab.x += __shfl_xor_sync(~0u, ab.x, 16); ab.y += __shfl_xor_sync(~0u, ab.y, 16);
    ab.z += __shfl_xor_sync(~0u, ab.z, 16); ab.w += __shfl_xor_sync(~0u, ab.w, 16);
    if (half == 0) {
        float inv = 1.f / fmaxf((float)(end - beg), 1.f);
        uint2 o;
        o.x = bf2(aa.x * inv, aa.y * inv); o.y = bf2(aa.z * inv, aa.w * inv);
        reinterpret_cast<uint2*>(d_hp)[(size_t)gw * 16 + c] = o;
        o.x = bf2(ab.x * inv, ab.y * inv); o.y = bf2(ab.z * inv, ab.w * inv);
        reinterpret_cast<uint2*>(d_hn)[(size_t)gw * 16 + c] = o;
    }
}

// ---------------- mma GEMM building blocks ----------------
// Tile: 128 nodes x 64 outs, 256 threads (8 warps). Warp w handles rows [w*16, w*16+16),
// all 64 cols (8 n-blocks), K via m16n8k8 tf32 mma. acc: float[32] (8 nb x 4).
#define XST 68
#define SM_X 0
#define SM_W (128 * XST)                 // floats
#define SM_B (SM_W + 64 * 64)
#define SM_C (SM_B + 64)
#define SM_TOTF (SM_C + 64)
#define GEMM_SMEM (SM_TOTF * 4)

__device__ __forceinline__ void stage_f32(float* __restrict__ Xs, const float* __restrict__ S,
                                          int node0, int n, int tid) {
    #pragma unroll
    for (int it = 0; it < 8; ++it) {
        int t = tid + it * 256;
        int r = t >> 4, c4 = (t & 15) << 2;
        int nd = node0 + r;
        float4 v = make_float4(0.f, 0.f, 0.f, 0.f);
        if (nd < n) v = __ldg(reinterpret_cast<const float4*>(S) + (size_t)nd * 16 + (t & 15));
        v.x = tf32r(v.x); v.y = tf32r(v.y); v.z = tf32r(v.z); v.w = tf32r(v.w);
        *reinterpret_cast<float4*>(Xs + r * XST + c4) = v;
    }
}
__device__ __forceinline__ void stage_bf16(float* __restrict__ Xs, const __nv_bfloat16* __restrict__ S,
                                           int node0, int n, int tid) {
    #pragma unroll
    for (int it = 0; it < 4; ++it) {
        int t = tid + it * 256;
        int r = t >> 3, u4 = t & 7;
        int nd = node0 + r;
        uint4 v = make_uint4(0u, 0u, 0u, 0u);
        if (nd < n) v = __ldg(reinterpret_cast<const uint4*>(S) + (size_t)nd * 8 + u4);
        float2 f0 = bf2f(v.x), f1 = bf2f(v.y), f2 = bf2f(v.z), f3 = bf2f(v.w);
        *reinterpret_cast<float4*>(Xs + r * XST + u4 * 8)     = make_float4(f0.x, f0.y, f1.x, f1.y);
        *reinterpret_cast<float4*>(Xs + r * XST + u4 * 8 + 4) = make_float4(f2.x, f2.y, f3.x, f3.y);
    }
}
__device__ __forceinline__ void stage_w(float* __restrict__ Wp, const float* __restrict__ Wg, int tid) {
    #pragma unroll
    for (int it = 0; it < 4; ++it) {
        int t = tid + it * 256;
        reinterpret_cast<float4*>(Wp)[t] = __ldg(reinterpret_cast<const float4*>(Wg) + t);
    }
}
__device__ __forceinline__ void mma_phase(const float* __restrict__ Xs, const float* __restrict__ Wp,
                                          float* acc, int r0w, int lane) {
    int ar = r0w + (lane >> 2);
    #pragma unroll
    for (int s = 0; s < 8; ++s) {
        int ac = s * 8 + (lane & 3);
        uint32_t a0 = __float_as_uint(Xs[ar * XST + ac]);
        uint32_t a1 = __float_as_uint(Xs[(ar + 8) * XST + ac]);
        uint32_t a2 = __float_as_uint(Xs[ar * XST + ac + 4]);
        uint32_t a3 = __float_as_uint(Xs[(ar + 8) * XST + ac + 4]);
        #pragma unroll
        for (int nb = 0; nb < 8; ++nb) {
            float2 b = *reinterpret_cast<const float2*>(Wp + (s * 8 + nb) * 64 + lane * 2);
            mma_tf32(acc + nb * 4, a0, a1, a2, a3, __float_as_uint(b.x), __float_as_uint(b.y));
        }
    }
}

// epilogue (layer 0): relu(acc + b + ind*cv) -> bf16 store
__device__ __forceinline__ void epi0(const float* acc, const float* __restrict__ sb,
                                     const float* __restrict__ sc, __nv_bfloat16* __restrict__ out,
                                     int node0, int r0w, int lane, int n) {
    int rA = node0 + r0w + (lane >> 2);
    int rB = rA + 8;
    float indA = (rA < n && d_cnt[rA] > 0) ? 1.f : 0.f;
    float indB = (rB < n && d_cnt[rB] > 0) ? 1.f : 0.f;
    uint32_t* o32 = reinterpret_cast<uint32_t*>(out);
    #pragma unroll
    for (int nb = 0; nb < 8; ++nb) {
        int cc = nb * 8 + (lane & 3) * 2;
        float xA0 = fmaxf(acc[nb*4+0] + sb[cc]   + indA * sc[cc],   0.f);
        float xA1 = fmaxf(acc[nb*4+1] + sb[cc+1] + indA * sc[cc+1], 0.f);
        float xB0 = fmaxf(acc[nb*4+2] + sb[cc]   + indB * sc[cc],   0.f);
        float xB1 = fmaxf(acc[nb*4+3] + sb[cc+1] + indB * sc[cc+1], 0.f);
        if (rA < n) o32[(size_t)rA * 32 + (cc >> 1)] = bf2(xA0, xA1);
        if (rB < n) o32[(size_t)rB * 32 + (cc >> 1)] = bf2(xB0, xB1);
    }
}

// ---------------- layer 0: shared base (nfeats,hagg0), two ef tails ----------------
__global__ void __launch_bounds__(256) k_l0(
    const float* __restrict__ nfeats, const float* __restrict__ bap, int n)
{
    extern __shared__ float sm[];
    float* Xs = sm + SM_X;
    float* Wp = sm + SM_W;
    float* sb = sm + SM_B;
    float* sc = sm + SM_C;
    int tid = threadIdx.x, wid = tid >> 5, lane = tid & 31;
    int node0 = blockIdx.x * 128;
    int r0w = wid * 16;
    if (tid < 64) { sb[tid] = bap[tid]; sc[tid] = d_cv[0][tid]; }

    float acc[32], accB[32];
    #pragma unroll
    for (int i = 0; i < 32; ++i) acc[i] = 0.f;

    // p0: nfeats (panel 0)
    stage_f32(Xs, nfeats, node0, n, tid);
    stage_w(Wp, d_Wf[0], tid);
    __syncthreads();
    mma_phase(Xs, Wp, acc, r0w, lane);
    __syncthreads();

    // p1: hagg0 (panel 1)
    stage_bf16(Xs, d_hagg0, node0, n, tid);
    stage_w(Wp, d_Wf[0] + 4096, tid);
    __syncthreads();
    mma_phase(Xs, Wp, acc, r0w, lane);
    __syncthreads();
    #pragma unroll
    for (int i = 0; i < 32; ++i) accB[i] = acc[i];

    // p2: efp (panel 2) -> h1p
    stage_bf16(Xs, d_efp, node0, n, tid);
    stage_w(Wp, d_Wf[0] + 8192, tid);
    __syncthreads();
    mma_phase(Xs, Wp, acc, r0w, lane);
    epi0(acc, sb, sc, d_h1p, node0, r0w, lane, n);
    __syncthreads();

    // p3: efn (panel 2 resident) -> h1n
    stage_bf16(Xs, d_efn, node0, n, tid);
    __syncthreads();
    #pragma unroll
    for (int i = 0; i < 32; ++i) acc[i] = accB[i];
    mma_phase(Xs, Wp, acc, r0w, lane);
    epi0(acc, sb, sc, d_h1n, node0, r0w, lane, n);
}

// ---------------- layer 1: blockIdx.y = view, fused BCE ----------------
__global__ void __launch_bounds__(256) k_l1(const float* __restrict__ bap, int n)
{
    extern __shared__ float sm[];
    float* Xs = sm + SM_X;
    float* Wp = sm + SM_W;
    float* sb = sm + SM_B;
    float* sc = sm + SM_C;
    __shared__ float wred[8];
    int tid = threadIdx.x, wid = tid >> 5, lane = tid & 31;
    int node0 = blockIdx.x * 128;
    int r0w = wid * 16;
    int view = blockIdx.y;
    if (tid < 64) { sb[tid] = bap[tid]; sc[tid] = d_cv[1][tid]; }

    const __nv_bfloat16* S0 = view ? d_h1n : d_h1p;
    const __nv_bfloat16* S1 = view ? d_hn  : d_hp;
    const __nv_bfloat16* S2 = view ? d_efn : d_efp;

    float acc[32];
    #pragma unroll
    for (int i = 0; i < 32; ++i) acc[i] = 0.f;

    #pragma unroll
    for (int p = 0; p < 3; ++p) {
        const __nv_bfloat16* S = (p == 0) ? S0 : (p == 1) ? S1 : S2;
        if (p) __syncthreads();
        stage_bf16(Xs, S, node0, n, tid);
        stage_w(Wp, d_Wf[1] + p * 4096, tid);
        __syncthreads();
        mma_phase(Xs, Wp, acc, r0w, lane);
    }

    // BCE epilogue
    int rA = node0 + r0w + (lane >> 2);
    int rB = rA + 8;
    float indA = (rA < n && d_cnt[rA] > 0) ? 1.f : 0.f;
    float indB = (rB < n && d_cnt[rB] > 0) ? 1.f : 0.f;
    float lsum = 0.f;
    #pragma unroll
    for (int nb = 0; nb < 8; ++nb) {
        int cc = nb * 8 + (lane & 3) * 2;
        float xA0 = fmaxf(acc[nb*4+0] + sb[cc]   + indA * sc[cc],   0.f);
        float xA1 = fmaxf(acc[nb*4+1] + sb[cc+1] + indA * sc[cc+1], 0.f);
        float xB0 = fmaxf(acc[nb*4+2] + sb[cc]   + indB * sc[cc],   0.f);
        float xB1 = fmaxf(acc[nb*4+3] + sb[cc+1] + indB * sc[cc+1], 0.f);
        if (rA < n) {
            float t0 = log1pf(expf(-xA0)), t1 = log1pf(expf(-xA1));
            lsum += view ? (xA0 + t0 + xA1 + t1) : (t0 + t1);
        }
        if (rB < n) {
            float t0 = log1pf(expf(-xB0)), t1 = log1pf(expf(-xB1));
            lsum += view ? (xB0 + t0 + xB1 + t1) : (t0 + t1);
        }
    }
    #pragma unroll
    for (int o = 16; o; o >>= 1) lsum += __shfl_down_sync(~0u, lsum, o);
    if (lane == 0) wred[wid] = lsum;
    __syncthreads();
    if (tid < 8) {
        float s = wred[tid];
        #pragma unroll
        for (int o = 4; o; o >>= 1) s += __shfl_down_sync(0xffu, s, o);
        if (tid == 0) atomicAdd(&d_loss, (double)s);
    }
}

__global__ void k_write(float* out, double denom) {
    out[0] = (float)(d_loss / denom);
}

// ---------------- launch ----------------
extern "C" void kernel_launch(void* const* d_in, const int* in_sizes, int n_in,
                              void* d_out, int out_size) {
    const float* nfeats = (const float*)d_in[0];
    const float* efeats = (const float*)d_in[1];
    const int*   src    = (const int*)d_in[2];
    const int*   dst    = (const int*)d_in[3];
    const int*   perm   = (const int*)d_in[4];
    const float* Wm0 = (const float*)d_in[5];
    const float* bm0 = (const float*)d_in[6];
    const float* Wa0 = (const float*)d_in[7];
    const float* ba0 = (const float*)d_in[8];
    const float* Wm1 = (const float*)d_in[9];
    const float* bm1 = (const float*)d_in[10];
    const float* Wa1 = (const float*)d_in[11];
    const float* ba1 = (const float*)d_in[12];

    int n = in_sizes[0] / 64;
    int E = in_sizes[2];
    int nb = (n + 1023) / 1024;

    cudaFuncSetAttribute(k_l0, cudaFuncAttributeMaxDynamicSharedMemorySize, GEMM_SMEM);
    cudaFuncSetAttribute(k_l1, cudaFuncAttributeMaxDynamicSharedMemorySize, GEMM_SMEM);

    int gw = (n * 32 + 255) / 256;  // one warp per node
    int gl = (n + 127) / 128;       // 128 nodes per tile

    k_init   <<<(n + 255) / 256, 256>>>(n);                  // 1
    k_hist   <<<(E + 255) / 256, 256>>>(dst, E);             // 2
    k_scan   <<<nb, 1024>>>(n, E, nb);                       // 3
    k_scatter<<<(E + 255) / 256, 256>>>(src, dst, perm, E);  // 4 <- profiled
    k_fold2  <<<2, 256>>>(Wm0, bm0, Wa0, Wm1, bm1, Wa1);     // 5
    k_agg3   <<<gw, 256>>>(nfeats, efeats, n);               // 6
    k_l0     <<<gl, 256, GEMM_SMEM>>>(nfeats, ba0, n);       // 7
    k_aggh2  <<<gw, 256>>>(n);                               // 8
    {
        dim3 grid(gl, 2);
        k_l1 <<<grid, 256, GEMM_SMEM>>>(ba1, n);             // 9
    }
    k_write  <<<1, 1>>>((float*)d_out, (double)n * 64.0);    // 10
}

// round 7
// speedup vs baseline: 2.2258x; 1.1101x over previous
#include <cuda_runtime.h>
#include <cuda_bf16.h>
#include <math.h>
#include <cstdint>

#define NN 100000
#define EE 1000000

// ---------------- device scratch (zero-initialized at load; k_clean restores) ----------------
__device__ int    d_cnt[NN];
__device__ int    d_off[NN + 1];
__device__ int    d_cur[NN];
__device__ int    d_scan_tix;
__device__ unsigned long long d_scan_state[128];
__device__ int4   d_adj[EE];                    // {ssrc, eid, pid, 0}
__device__ __nv_bfloat16 d_hagg0[(size_t)NN * 64];
__device__ __nv_bfloat16 d_efp [(size_t)NN * 64];
__device__ __nv_bfloat16 d_efn [(size_t)NN * 64];
__device__ __nv_bfloat16 d_h1p [(size_t)NN * 64];
__device__ __nv_bfloat16 d_h1n [(size_t)NN * 64];
__device__ __nv_bfloat16 d_hp  [(size_t)NN * 64];
__device__ __nv_bfloat16 d_hn  [(size_t)NN * 64];
// folded W in tf32, stored in exact mma B-fragment order
__device__ float  d_Wf[2][3 * 8 * 8 * 64];
__device__ float  d_cv[2][64];
__device__ double d_loss;

// ---------------- helpers ----------------
__device__ __forceinline__ float tf32r(float x) {
    uint32_t r; asm("cvt.rna.tf32.f32 %0, %1;" : "=r"(r) : "f"(x));
    return __uint_as_float(r);
}
__device__ __forceinline__ void mma_tf32(float* c, uint32_t a0, uint32_t a1, uint32_t a2, uint32_t a3,
                                         uint32_t b0, uint32_t b1) {
    asm volatile("mma.sync.aligned.m16n8k8.row.col.f32.tf32.tf32.f32 "
                 "{%0,%1,%2,%3}, {%4,%5,%6,%7}, {%8,%9}, {%0,%1,%2,%3};"
                 : "+f"(c[0]), "+f"(c[1]), "+f"(c[2]), "+f"(c[3])
                 : "r"(a0), "r"(a1), "r"(a2), "r"(a3), "r"(b0), "r"(b1));
}
__device__ __forceinline__ uint32_t bf2(float x, float y) {
    uint32_t r; asm("cvt.rn.satfinite.bf16x2.f32 %0, %1, %2;" : "=r"(r) : "f"(y), "f"(x)); return r;
}
__device__ __forceinline__ float2 bf2f(uint32_t v) {
    __nv_bfloat162 h = *reinterpret_cast<__nv_bfloat162*>(&v);
    return __bfloat1622float2(h);
}

// ---------------- CSR build ----------------
__global__ void k_hist(const int* __restrict__ dst, int E) {
    int e = blockIdx.x * blockDim.x + threadIdx.x;
    if (e < E) atomicAdd(&d_cnt[dst[e]], 1);
}

__global__ void k_scan(int n, int E, int nb) {
    __shared__ int ws[32];
    __shared__ int s_bid;
    __shared__ int s_pref;
    if (threadIdx.x == 0) s_bid = atomicAdd(&d_scan_tix, 1);
    __syncthreads();
    int bid = s_bid;
    int i = bid * 1024 + threadIdx.x;
    int lane = threadIdx.x & 31, wid = threadIdx.x >> 5;
    int v = (i < n) ? d_cnt[i] : 0;
    int x = v;
    #pragma unroll
    for (int o = 1; o < 32; o <<= 1) { int y = __shfl_up_sync(~0u, x, o); if (lane >= o) x += y; }
    if (lane == 31) ws[wid] = x;
    __syncthreads();
    if (wid == 0) {
        int w = ws[lane];
        #pragma unroll
        for (int o = 1; o < 32; o <<= 1) { int y = __shfl_up_sync(~0u, w, o); if (lane >= o) w += y; }
        ws[lane] = w;
    }
    __syncthreads();
    int incl = x + (wid > 0 ? ws[wid - 1] : 0);
    int total = ws[31];
    if (threadIdx.x == 0) {
        if (bid == 0) {
            atomicExch(&d_scan_state[0], (2ULL << 32) | (unsigned)total);
            s_pref = 0;
        } else {
            atomicExch(&d_scan_state[bid], (1ULL << 32) | (unsigned)total);
            int pref = 0;
            for (int j = bid - 1; j >= 0; --j) {
                unsigned long long st;
                do { st = atomicAdd(&d_scan_state[j], 0ULL); } while (!(st >> 32));
                pref += (int)(unsigned)st;
                if ((st >> 32) == 2ULL) break;
            }
            atomicExch(&d_scan_state[bid], (2ULL << 32) | (unsigned)(pref + total));
            s_pref = pref;
        }
    }
    __syncthreads();
    int pref = s_pref;
    if (i < n) d_off[i] = pref + incl - v;
    if (bid == nb - 1 && threadIdx.x == 0) d_off[n] = E;
}

__global__ void k_scatter(const int* __restrict__ src, const int* __restrict__ dst,
                          const int* __restrict__ perm, int E) {
    int e = blockIdx.x * blockDim.x + threadIdx.x;
    if (e < E) {
        int d = dst[e];
        int p = d_off[d] + atomicAdd(&d_cur[d], 1);
        d_adj[p] = make_int4(src[e], e, perm[e], 0);
    }
}

// ---------------- fused first-stage aggregation (fp32 in, bf16 out) ----------------
__global__ void k_agg3(const float* __restrict__ nf, const float* __restrict__ ef, int n) {
    int gw = (blockIdx.x * blockDim.x + threadIdx.x) >> 5;
    int lane = threadIdx.x & 31;
    if (gw >= n) return;
    int beg = d_off[gw], end = d_off[gw + 1];
    int half = lane >> 4;
    int c = lane & 15;
    float4 ah = make_float4(0.f, 0.f, 0.f, 0.f);
    float4 ap = ah, an = ah;
    for (int k = beg + half; k < end; k += 2) {
        int4 a = __ldg(&d_adj[k]);
        float4 v1 = __ldg((const float4*)nf + (size_t)a.x * 16 + c);
        float4 v2 = __ldg((const float4*)ef + (size_t)a.y * 16 + c);
        float4 v3 = __ldg((const float4*)ef + (size_t)a.z * 16 + c);
        ah.x += v1.x; ah.y += v1.y; ah.z += v1.z; ah.w += v1.w;
        ap.x += v2.x; ap.y += v2.y; ap.z += v2.z; ap.w += v2.w;
        an.x += v3.x; an.y += v3.y; an.z += v3.z; an.w += v3.w;
    }
    ah.x += __shfl_xor_sync(~0u, ah.x, 16); ah.y += __shfl_xor_sync(~0u, ah.y, 16);
    ah.z += __shfl_xor_sync(~0u, ah.z, 16); ah.w += __shfl_xor_sync(~0u, ah.w, 16);
    ap.x += __shfl_xor_sync(~0u, ap.x, 16); ap.y += __shfl_xor_sync(~0u, ap.y, 16);
    ap.z += __shfl_xor_sync(~0u, ap.z, 16); ap.w += __shfl_xor_sync(~0u, ap.w, 16);
    an.x += __shfl_xor_sync(~0u, an.x, 16); an.y += __shfl_xor_sync(~0u, an.y, 16);
    an.z += __shfl_xor_sync(~0u, an.z, 16); an.w += __shfl_xor_sync(~0u, an.w, 16);
    if (half == 0) {
        float inv = 1.f / fmaxf((float)(end - beg), 1.f);
        uint2 o;
        o.x = bf2(ah.x * inv, ah.y * inv); o.y = bf2(ah.z * inv, ah.w * inv);
        reinterpret_cast<uint2*>(d_hagg0)[(size_t)gw * 16 + c] = o;
        o.x = bf2(ap.x * inv, ap.y * inv); o.y = bf2(ap.z * inv, ap.w * inv);
        reinterpret_cast<uint2*>(d_efp)[(size_t)gw * 16 + c] = o;
        o.x = bf2(an.x * inv, an.y * inv); o.y = bf2(an.z * inv, an.w * inv);
        reinterpret_cast<uint2*>(d_efn)[(size_t)gw * 16 + c] = o;
    }
}

// ---------------- second-stage aggregation: hp + hn (bf16 in/out) ----------------
__global__ void k_aggh2(int n) {
    int gw = (blockIdx.x * blockDim.x + threadIdx.x) >> 5;
    int lane = threadIdx.x & 31;
    if (gw >= n) return;
    int beg = d_off[gw], end = d_off[gw + 1];
    int half = lane >> 4;
    int c = lane & 15;
    float4 aa = make_float4(0.f, 0.f, 0.f, 0.f);
    float4 ab = aa;
    const uint2* fa = reinterpret_cast<const uint2*>(d_h1p);
    const uint2* fb = reinterpret_cast<const uint2*>(d_h1n);
    for (int k = beg + half; k < end; k += 2) {
        int s = __ldg(&d_adj[k]).x;
        uint2 v1 = __ldg(fa + (size_t)s * 16 + c);
        uint2 v2 = __ldg(fb + (size_t)s * 16 + c);
        float2 a0 = bf2f(v1.x), a1 = bf2f(v1.y);
        float2 b0 = bf2f(v2.x), b1 = bf2f(v2.y);
        aa.x += a0.x; aa.y += a0.y; aa.z += a1.x; aa.w += a1.y;
        ab.x += b0.x; ab.y += b0.y; ab.z += b1.x; ab.w += b1.y;
    }
    aa.x += __shfl_xor_sync(~0u, aa.x, 16); aa.y += __shfl_xor_sync(~0u, aa.y, 16);
    aa.z += __shfl_xor_sync(~0u, aa.z, 16); aa.w += __shfl_xor_sync(~0u, aa.w, 16);
    ab.x += __shfl_xor_sync(~0u, ab.x, 16); ab.y += __shfl_xor_sync(~0u, ab.y, 16);
    ab.z += __shfl_xor_sync(~0u, ab.z, 16); ab.w += __shfl_xor_sync(~0u, ab.w, 16);
    if (half == 0) {
        float inv = 1.f / fmaxf((float)(end - beg), 1.f);
        uint2 o;
        o.x = bf2(aa.x * inv, aa.y * inv); o.y = bf2(aa.z * inv, aa.w * inv);
        reinterpret_cast<uint2*>(d_hp)[(size_t)gw * 16 + c] = o;
        o.x = bf2(ab.x * inv, ab.y * inv); o.y = bf2(ab.z * inv, ab.w * inv);
        reinterpret_cast<uint2*>(d_hn)[(size_t)gw * 16 + c] = o;
    }
}

// ---------------- fold Wmsg into Wapply -> tf32 B-fragment layout ----------------
__global__ void k_fold2(const float* __restrict__ Wm0, const float* __restrict__ bm0,
                        const float* __restrict__ Wa0,
                        const float* __restrict__ Wm1, const float* __restrict__ bm1,
                        const float* __restrict__ Wa1) {
    int layer = blockIdx.x;
    const float* Wmsg = layer ? Wm1 : Wm0;
    const float* bmsg = layer ? bm1 : bm0;
    const float* Wap  = layer ? Wa1 : Wa0;
    __shared__ float Wn[64][64];
    __shared__ float bm[64];
    int tid = threadIdx.x;
    for (int idx = tid; idx < 64 * 64; idx += 256) {
        int j = idx >> 6, t = idx & 63;
        Wn[t][j] = Wap[j * 128 + 64 + t];
    }
    if (tid < 64) bm[tid] = bmsg[tid];
    __syncthreads();
    for (int idx = tid; idx < 192 * 64; idx += 256) {
        int k = idx >> 6, j = idx & 63;
        float r;
        if (k < 64) {
            r = Wap[j * 128 + k];
        } else {
            int col = k - 64;
            float a = 0.f;
            #pragma unroll
            for (int t = 0; t < 64; ++t) a += Wmsg[t * 128 + col] * Wn[t][j];
            r = a;
        }
        int panel = k >> 6, kk = k & 63;
        int s = kk >> 3, krem = kk & 7;
        int slot = krem >> 2, kq = krem & 3;
        int t = ((j & 7) << 2) | kq;
        int nb = j >> 3;
        int o = ((panel * 8 + s) * 8 + nb) * 64 + t * 2 + slot;
        d_Wf[layer][o] = tf32r(r);
    }
    for (int j = tid; j < 64; j += 256) {
        float a = 0.f;
        #pragma unroll
        for (int t = 0; t < 64; ++t) a += bm[t] * Wn[t][j];
        d_cv[layer][j] = a;
    }
}

// ---------------- mma GEMM building blocks ----------------
#define XST 68
#define SM_X 0
#define SM_W (128 * XST)
#define SM_B (SM_W + 64 * 64)
#define SM_C (SM_B + 64)
#define SM_TOTF (SM_C + 64)
#define GEMM_SMEM (SM_TOTF * 4)

__device__ __forceinline__ void stage_f32(float* __restrict__ Xs, const float* __restrict__ S,
                                          int node0, int n, int tid) {
    #pragma unroll
    for (int it = 0; it < 8; ++it) {
        int t = tid + it * 256;
        int r = t >> 4, c4 = (t & 15) << 2;
        int nd = node0 + r;
        float4 v = make_float4(0.f, 0.f, 0.f, 0.f);
        if (nd < n) v = __ldg(reinterpret_cast<const float4*>(S) + (size_t)nd * 16 + (t & 15));
        v.x = tf32r(v.x); v.y = tf32r(v.y); v.z = tf32r(v.z); v.w = tf32r(v.w);
        *reinterpret_cast<float4*>(Xs + r * XST + c4) = v;
    }
}
__device__ __forceinline__ void stage_bf16(float* __restrict__ Xs, const __nv_bfloat16* __restrict__ S,
                                           int node0, int n, int tid) {
    #pragma unroll
    for (int it = 0; it < 4; ++it) {
        int t = tid + it * 256;
        int r = t >> 3, u4 = t & 7;
        int nd = node0 + r;
        uint4 v = make_uint4(0u, 0u, 0u, 0u);
        if (nd < n) v = __ldg(reinterpret_cast<const uint4*>(S) + (size_t)nd * 8 + u4);
        float2 f0 = bf2f(v.x), f1 = bf2f(v.y), f2 = bf2f(v.z), f3 = bf2f(v.w);
        *reinterpret_cast<float4*>(Xs + r * XST + u4 * 8)     = make_float4(f0.x, f0.y, f1.x, f1.y);
        *reinterpret_cast<float4*>(Xs + r * XST + u4 * 8 + 4) = make_float4(f2.x, f2.y, f3.x, f3.y);
    }
}
__device__ __forceinline__ void stage_w(float* __restrict__ Wp, const float* __restrict__ Wg, int tid) {
    #pragma unroll
    for (int it = 0; it < 4; ++it) {
        int t = tid + it * 256;
        reinterpret_cast<float4*>(Wp)[t] = __ldg(reinterpret_cast<const float4*>(Wg) + t);
    }
}
__device__ __forceinline__ void mma_phase(const float* __restrict__ Xs, const float* __restrict__ Wp,
                                          float* acc, int r0w, int lane) {
    int ar = r0w + (lane >> 2);
    #pragma unroll
    for (int s = 0; s < 8; ++s) {
        int ac = s * 8 + (lane & 3);
        uint32_t a0 = __float_as_uint(Xs[ar * XST + ac]);
        uint32_t a1 = __float_as_uint(Xs[(ar + 8) * XST + ac]);
        uint32_t a2 = __float_as_uint(Xs[ar * XST + ac + 4]);
        uint32_t a3 = __float_as_uint(Xs[(ar + 8) * XST + ac + 4]);
        #pragma unroll
        for (int nb = 0; nb < 8; ++nb) {
            float2 b = *reinterpret_cast<const float2*>(Wp + (s * 8 + nb) * 64 + lane * 2);
            mma_tf32(acc + nb * 4, a0, a1, a2, a3, __float_as_uint(b.x), __float_as_uint(b.y));
        }
    }
}

__device__ __forceinline__ float indf(int nd, int n) {
    return (nd < n && d_off[nd + 1] > d_off[nd]) ? 1.f : 0.f;
}

__device__ __forceinline__ void epi0(const float* acc, const float* __restrict__ sb,
                                     const float* __restrict__ sc, __nv_bfloat16* __restrict__ out,
                                     int node0, int r0w, int lane, int n) {
    int rA = node0 + r0w + (lane >> 2);
    int rB = rA + 8;
    float indA = indf(rA, n), indB = indf(rB, n);
    uint32_t* o32 = reinterpret_cast<uint32_t*>(out);
    #pragma unroll
    for (int nb = 0; nb < 8; ++nb) {
        int cc = nb * 8 + (lane & 3) * 2;
        float xA0 = fmaxf(acc[nb*4+0] + sb[cc]   + indA * sc[cc],   0.f);
        float xA1 = fmaxf(acc[nb*4+1] + sb[cc+1] + indA * sc[cc+1], 0.f);
        float xB0 = fmaxf(acc[nb*4+2] + sb[cc]   + indB * sc[cc],   0.f);
        float xB1 = fmaxf(acc[nb*4+3] + sb[cc+1] + indB * sc[cc+1], 0.f);
        if (rA < n) o32[(size_t)rA * 32 + (cc >> 1)] = bf2(xA0, xA1);
        if (rB < n) o32[(size_t)rB * 32 + (cc >> 1)] = bf2(xB0, xB1);
    }
}

// ---------------- layer 0 ----------------
__global__ void __launch_bounds__(256) k_l0(
    const float* __restrict__ nfeats, const float* __restrict__ bap, int n)
{
    extern __shared__ float sm[];
    float* Xs = sm + SM_X;
    float* Wp = sm + SM_W;
    float* sb = sm + SM_B;
    float* sc = sm + SM_C;
    int tid = threadIdx.x, wid = tid >> 5, lane = tid & 31;
    int node0 = blockIdx.x * 128;
    int r0w = wid * 16;
    if (tid < 64) { sb[tid] = bap[tid]; sc[tid] = d_cv[0][tid]; }

    float acc[32], accB[32];
    #pragma unroll
    for (int i = 0; i < 32; ++i) acc[i] = 0.f;

    stage_f32(Xs, nfeats, node0, n, tid);
    stage_w(Wp, d_Wf[0], tid);
    __syncthreads();
    mma_phase(Xs, Wp, acc, r0w, lane);
    __syncthreads();

    stage_bf16(Xs, d_hagg0, node0, n, tid);
    stage_w(Wp, d_Wf[0] + 4096, tid);
    __syncthreads();
    mma_phase(Xs, Wp, acc, r0w, lane);
    __syncthreads();
    #pragma unroll
    for (int i = 0; i < 32; ++i) accB[i] = acc[i];

    stage_bf16(Xs, d_efp, node0, n, tid);
    stage_w(Wp, d_Wf[0] + 8192, tid);
    __syncthreads();
    mma_phase(Xs, Wp, acc, r0w, lane);
    epi0(acc, sb, sc, d_h1p, node0, r0w, lane, n);
    __syncthreads();

    stage_bf16(Xs, d_efn, node0, n, tid);
    __syncthreads();
    #pragma unroll
    for (int i = 0; i < 32; ++i) acc[i] = accB[i];
    mma_phase(Xs, Wp, acc, r0w, lane);
    epi0(acc, sb, sc, d_h1n, node0, r0w, lane, n);
}

// ---------------- layer 1 ----------------
__global__ void __launch_bounds__(256) k_l1(const float* __restrict__ bap, int n)
{
    extern __shared__ float sm[];
    float* Xs = sm + SM_X;
    float* Wp = sm + SM_W;
    float* sb = sm + SM_B;
    float* sc = sm + SM_C;
    __shared__ float wred[8];
    int tid = threadIdx.x, wid = tid >> 5, lane = tid & 31;
    int node0 = blockIdx.x * 128;
    int r0w = wid * 16;
    int view = blockIdx.y;
    if (tid < 64) { sb[tid] = bap[tid]; sc[tid] = d_cv[1][tid]; }

    const __nv_bfloat16* S0 = view ? d_h1n : d_h1p;
    const __nv_bfloat16* S1 = view ? d_hn  : d_hp;
    const __nv_bfloat16* S2 = view ? d_efn : d_efp;

    float acc[32];
    #pragma unroll
    for (int i = 0; i < 32; ++i) acc[i] = 0.f;

    #pragma unroll
    for (int p = 0; p < 3; ++p) {
        const __nv_bfloat16* S = (p == 0) ? S0 : (p == 1) ? S1 : S2;
        if (p) __syncthreads();
        stage_bf16(Xs, S, node0, n, tid);
        stage_w(Wp, d_Wf[1] + p * 4096, tid);
        __syncthreads();
        mma_phase(Xs, Wp, acc, r0w, lane);
    }

    int rA = node0 + r0w + (lane >> 2);
    int rB = rA + 8;
    float indA = indf(rA, n), indB = indf(rB, n);
    float lsum = 0.f;
    #pragma unroll
    for (int nb = 0; nb < 8; ++nb) {
        int cc = nb * 8 + (lane & 3) * 2;
        float xA0 = fmaxf(acc[nb*4+0] + sb[cc]   + indA * sc[cc],   0.f);
        float xA1 = fmaxf(acc[nb*4+1] + sb[cc+1] + indA * sc[cc+1], 0.f);
        float xB0 = fmaxf(acc[nb*4+2] + sb[cc]   + indB * sc[cc],   0.f);
        float xB1 = fmaxf(acc[nb*4+3] + sb[cc+1] + indB * sc[cc+1], 0.f);
        if (rA < n) {
            float t0 = log1pf(expf(-xA0)), t1 = log1pf(expf(-xA1));
            lsum += view ? (xA0 + t0 + xA1 + t1) : (t0 + t1);
        }
        if (rB < n) {
            float t0 = log1pf(expf(-xB0)), t1 = log1pf(expf(-xB1));
            lsum += view ? (xB0 + t0 + xB1 + t1) : (t0 + t1);
        }
    }
    #pragma unroll
    for (int o = 16; o; o >>= 1) lsum += __shfl_down_sync(~0u, lsum, o);
    if (lane == 0) wred[wid] = lsum;
    __syncthreads();
    if (tid < 8) {
        float s = wred[tid];
        #pragma unroll
        for (int o = 4; o; o >>= 1) s += __shfl_down_sync(0xffu, s, o);
        if (tid == 0) atomicAdd(&d_loss, (double)s);
    }
}

// ---------------- write result + restore zero-state invariant ----------------
__global__ void k_clean(float* out, double denom, int n) {
    int i = blockIdx.x * blockDim.x + threadIdx.x;
    if (i == 0) {
        out[0] = (float)(d_loss / denom);
        d_loss = 0.0;
        d_scan_tix = 0;
    }
    if (i < 128) d_scan_state[i] = 0ULL;
    if (i < n) { d_cnt[i] = 0; d_cur[i] = 0; }
}

// ---------------- launch ----------------
extern "C" void kernel_launch(void* const* d_in, const int* in_sizes, int n_in,
                              void* d_out, int out_size) {
    const float* nfeats = (const float*)d_in[0];
    const float* efeats = (const float*)d_in[1];
    const int*   src    = (const int*)d_in[2];
    const int*   dst    = (const int*)d_in[3];
    const int*   perm   = (const int*)d_in[4];
    const float* Wm0 = (const float*)d_in[5];
    const float* bm0 = (const float*)d_in[6];
    const float* Wa0 = (const float*)d_in[7];
    const float* ba0 = (const float*)d_in[8];
    const float* Wm1 = (const float*)d_in[9];
    const float* bm1 = (const float*)d_in[10];
    const float* Wa1 = (const float*)d_in[11];
    const float* ba1 = (const float*)d_in[12];

    int n = in_sizes[0] / 64;
    int E = in_sizes[2];
    int nb = (n + 1023) / 1024;

    cudaFuncSetAttribute(k_l0, cudaFuncAttributeMaxDynamicSharedMemorySize, GEMM_SMEM);
    cudaFuncSetAttribute(k_l1, cudaFuncAttributeMaxDynamicSharedMemorySize, GEMM_SMEM);

    int gw = (n * 32 + 255) / 256;  // one warp per node
    int gl = (n + 127) / 128;       // 128 nodes per tile

    // state invariant: d_cnt/d_cur/d_scan_*/d_loss are zero on entry
    // (zero-init at load; k_clean restores after every call)
    k_hist   <<<(E + 255) / 256, 256>>>(dst, E);             // 1
    k_scan   <<<nb, 1024>>>(n, E, nb);                       // 2
    k_scatter<<<(E + 255) / 256, 256>>>(src, dst, perm, E);  // 3
    k_agg3   <<<gw, 256>>>(nfeats, efeats, n);               // 4 <- profiled
    k_fold2  <<<2, 256>>>(Wm0, bm0, Wa0, Wm1, bm1, Wa1);     // 5
    k_l0     <<<gl, 256, GEMM_SMEM>>>(nfeats, ba0, n);       // 6
    k_aggh2  <<<gw, 256>>>(n);                               // 7
    {
        dim3 grid(gl, 2);
        k_l1 <<<grid, 256, GEMM_SMEM>>>(ba1, n);             // 8
    }
    k_clean  <<<(n + 255) / 256, 256>>>((float*)d_out, (double)n * 64.0, n); // 9
}